// round 17
// baseline (speedup 1.0000x reference)
#include <cuda_runtime.h>
#include <math.h>

#define B 8
#define D 4
#define L 32
#define N 541696          // 736*736
#define NV (N/4)          // 135424 float4 groups
#define NW 8              // warps per block (256 threads)
#define GX 92             // blocks per batch; 92*8=736 <= 740 resident capacity
#define TOTAL_BLOCKS (GX * B)
#define CHUNK (NV / GX)   // 1472 float4-groups per block (exact: 92*1472=135424)
#define DELTA_AGG 0.5f
#define DELTA_DIS 1.5f
#define REG_W 0.001f

// ---- scratch (device globals; zero-init at load; finalizer re-zeroes) ----
__device__ float g_cntk[B][L];
__device__ float g_cnt[B][L];
__device__ float g_sumv[B][L];
__device__ float g_sumk[B][L][D];

// sense-reversing grid barriers (self-resetting across graph replays)
__device__ unsigned int g_bcnt[2];
__device__ volatile unsigned int g_brel[2];

__device__ __forceinline__ float fast_sqrt(float x) {
    float r; asm("sqrt.approx.f32 %0, %1;" : "=f"(r) : "f"(x)); return r;
}

// all TOTAL_BLOCKS CTAs are resident by construction -> cannot deadlock
__device__ __forceinline__ void gridbar(int k) {
    __syncthreads();
    if (threadIdx.x == 0) {
        unsigned int sense = g_brel[k];
        __threadfence();                       // release my prior global writes
        unsigned int old = atomicAdd(&g_bcnt[k], 1u);
        if (old == (unsigned)TOTAL_BLOCKS - 1u) {
            g_bcnt[k] = 0;                     // all arrived; safe to reset
            __threadfence();
            g_brel[k] = sense + 1u;            // release everyone
        } else {
            while (g_brel[k] == sense) __nanosleep(32);
        }
        __threadfence();                       // acquire
    }
    __syncthreads();
}

__device__ __forceinline__ float warpsum(float v) {
    #pragma unroll
    for (int o = 16; o > 0; o >>= 1) v += __shfl_xor_sync(0xFFFFFFFFu, v, o);
    return v;
}

// ---- fully fused: phase A -> bar -> phase B -> bar -> in-kernel finalize ----
__global__ void __launch_bounds__(256, 5) k_fused(
    const float* __restrict__ emb, const int* __restrict__ inst,
    const float* __restrict__ ker, const float* __restrict__ tmk,
    float* __restrict__ out)
{
    const int b  = blockIdx.y;
    const int g0 = blockIdx.x * CHUNK;

    __shared__ int    s_icnt[NW][L];     // low 16: cnt, high 16: cntk
    __shared__ float  s_sumk[NW][L][D];  // 4 fields in 4 consecutive banks
    __shared__ uchar4 s_lab[CHUNK];      // masked labels, block-local
    __shared__ float4 s_mean[L];
    __shared__ float  s_sv[NW][L];

    for (int i = threadIdx.x; i < NW * L; i += 256) ((int*)s_icnt)[i] = 0;
    for (int i = threadIdx.x; i < NW * L * D; i += 256) ((float*)s_sumk)[i] = 0.0f;
    for (int i = threadIdx.x; i < NW * L; i += 256) ((float*)s_sv)[i] = 0.0f;
    __syncthreads();

    const int wid = threadIdx.x >> 5;
    int*   myc = s_icnt[wid];
    float (*mys)[D] = s_sumk[wid];

    const float4* e0 = (const float4*)(emb + (size_t)b * D * N);
    const float4* e1 = e0 + NV;
    const float4* e2 = e0 + 2 * NV;
    const float4* e3 = e0 + 3 * NV;
    const int4*   ib = (const int4*)(inst + (size_t)b * N);
    const float4* kb = (const float4*)(ker + (size_t)b * N);
    const float4* mb = (const float4*)(tmk + (size_t)b * N);

    // ---------------- phase A ----------------
    for (int j = threadIdx.x; j < CHUNK; j += 256) {
        const int i = g0 + j;
        int4   lv = ib[i];
        float4 kv = kb[i];
        float4 mv = mb[i];
        float4 a  = e0[i];
        float4 c  = e1[i];
        float4 d2 = e2[i];
        float4 f  = e3[i];

        uchar4 lo;
        lo.x = (mv.x > 0.5f) ? (unsigned char)lv.x : 0;
        lo.y = (mv.y > 0.5f) ? (unsigned char)lv.y : 0;
        lo.z = (mv.z > 0.5f) ? (unsigned char)lv.z : 0;
        lo.w = (mv.w > 0.5f) ? (unsigned char)lv.w : 0;
        s_lab[j] = lo;

#define PIX1(LI, KK, X)                                                \
        {                                                              \
            int li = (LI);                                             \
            if (li != 0) {                                             \
                bool kn = (KK) > 0.5f;                                 \
                atomicAdd(&myc[li], kn ? 0x10001 : 1);                 \
                if (kn) {                                              \
                    atomicAdd(&mys[li][0], a.X);                       \
                    atomicAdd(&mys[li][1], c.X);                       \
                    atomicAdd(&mys[li][2], d2.X);                      \
                    atomicAdd(&mys[li][3], f.X);                       \
                }                                                      \
            }                                                          \
        }
        PIX1(lo.x, kv.x, x)
        PIX1(lo.y, kv.y, y)
        PIX1(lo.z, kv.z, z)
        PIX1(lo.w, kv.w, w)
#undef PIX1
    }
    __syncthreads();

    // flush block partials to global
    if (threadIdx.x < L) {
        int l = threadIdx.x;
        int s = 0;
        #pragma unroll
        for (int w = 0; w < NW; w++) s += s_icnt[w][l];
        if (s != 0) {
            atomicAdd(&g_cnt[b][l],  (float)(s & 0xFFFF));
            int ck = s >> 16;
            if (ck) atomicAdd(&g_cntk[b][l], (float)ck);
        }
    } else if (threadIdx.x < 160) {
        int t = threadIdx.x - L;
        int l = t >> 2, fld = t & 3;
        float s = 0.0f;
        #pragma unroll
        for (int w = 0; w < NW; w++) s += s_sumk[w][l][fld];
        if (s != 0.0f) atomicAdd(&g_sumk[b][l][fld], s);
    }

    gridbar(0);

    // ---------------- phase B ----------------
    if (threadIdx.x < L * D) {    // compute emb_mean from global accumulators
        int l = threadIdx.x >> 2, d = threadIdx.x & 3;
        float c = __ldcg(&g_cntk[b][l]);
        float s = __ldcg(&g_sumk[b][l][d]);
        ((float*)s_mean)[threadIdx.x] = (l == 0) ? 0.0f : s / fmaxf(c, 1.0f);
    }
    __syncthreads();

    float* my = s_sv[wid];
    for (int j = threadIdx.x; j < CHUNK; j += 256) {
        const int i = g0 + j;
        uchar4 lv = s_lab[j];
        float4 a  = e0[i];       // same chunk this block streamed: L2-hot
        float4 c  = e1[i];
        float4 d2 = e2[i];
        float4 f  = e3[i];

#define PIX2(LI, X)                                                    \
        {                                                              \
            int li = (LI);                                             \
            if (li != 0) {                                             \
                float4 mu = s_mean[li];                                \
                float dx = a.X  - mu.x;                                \
                float dy = c.X  - mu.y;                                \
                float dz = d2.X - mu.z;                                \
                float dw = f.X  - mu.w;                                \
                float sq = fmaf(dx, dx, fmaf(dy, dy,                   \
                            fmaf(dz, dz, dw * dw)));                   \
                float r = fmaxf(fast_sqrt(sq) - DELTA_AGG, 0.0f);      \
                atomicAdd(&my[li], __logf(fmaf(r, r, 1.0f)));          \
            }                                                          \
        }
        PIX2(lv.x, x)
        PIX2(lv.y, y)
        PIX2(lv.z, z)
        PIX2(lv.w, w)
#undef PIX2
    }
    __syncthreads();

    if (threadIdx.x < L) {
        int l = threadIdx.x;
        float s = 0.0f;
        #pragma unroll
        for (int w = 0; w < NW; w++) s += s_sv[w][l];
        if (s != 0.0f) atomicAdd(&g_sumv[b][l], s);
    }

    gridbar(1);

    // ---------------- in-kernel finalize (block x==0 of each batch, warp 0) ----
    if (blockIdx.x != 0 || threadIdx.x >= 32) return;

    int l = threadIdx.x;

    float ckraw = __ldcg(&g_cntk[b][l]);
    float cn    = __ldcg(&g_cnt[b][l]);
    float sv    = __ldcg(&g_sumv[b][l]);
    float s0    = __ldcg(&g_sumk[b][l][0]);
    float s1    = __ldcg(&g_sumk[b][l][1]);
    float s2    = __ldcg(&g_sumk[b][l][2]);
    float s3    = __ldcg(&g_sumk[b][l][3]);
    float cdiv  = fmaxf(ckraw, 1.0f);
    float m0 = (l == 0) ? 0.0f : s0 / cdiv;
    float m1 = (l == 0) ? 0.0f : s1 / cdiv;
    float m2 = (l == 0) ? 0.0f : s2 / cdiv;
    float m3 = (l == 0) ? 0.0f : s3 / cdiv;

    // re-zero this batch's accumulators for the next graph replay
    g_cntk[b][l] = 0.0f;
    g_cnt[b][l]  = 0.0f;
    g_sumv[b][l] = 0.0f;
    g_sumk[b][l][0] = 0.0f;
    g_sumk[b][l][1] = 0.0f;
    g_sumk[b][l][2] = 0.0f;
    g_sumk[b][l][3] = 0.0f;

    float ck  = ckraw;
    float tot = warpsum(ck);           // sum over l>0 (g_cntk[b][0] == 0)
    if (l == 0) ck = (float)N - tot;   // pixels with inst_k == 0

    bool present = ck > 0.0f;
    bool nzf     = present && (l > 0);
    unsigned pres_mask = __ballot_sync(0xFFFFFFFFu, present);
    unsigned nz_mask   = __ballot_sync(0xFFFFFFFFu, nzf);
    int num_instance   = __popc(pres_mask);

    // aggregation loss
    float la = nzf ? sv / fmaxf(cn, 1.0f) : 0.0f;
    float l_agg = warpsum(la) / fmaxf((float)(num_instance - 1), 1.0f);

    // discrimination loss: all distinct nz pairs via shuffles
    float dsum = 0.0f;
    int   npl  = 0;
    #pragma unroll
    for (int m = 0; m < 32; m++) {
        float om0 = __shfl_sync(0xFFFFFFFFu, m0, m);
        float om1 = __shfl_sync(0xFFFFFFFFu, m1, m);
        float om2 = __shfl_sync(0xFFFFFFFFu, m2, m);
        float om3 = __shfl_sync(0xFFFFFFFFu, m3, m);
        if (nzf && ((nz_mask >> m) & 1u) && m != l) {
            float dx = m0 - om0, dy = m1 - om1, dz = m2 - om2, dw = m3 - om3;
            float sq = dx*dx + dy*dy + dz*dz + dw*dw;
            float r = fmaxf(2.0f * DELTA_DIS - fast_sqrt(sq), 0.0f);
            dsum += __logf(fmaf(r, r, 1.0f));
            npl++;
        }
    }
    float n_pairs = warpsum((float)npl);
    float l_dis = warpsum(dsum) / fmaxf(n_pairs, 1.0f);
    l_dis = (num_instance > 2) ? l_dis : 0.0f;

    // regularizer (l==0 mean is zero -> contributes 0 but counts in denom)
    float msq = m0*m0 + m1*m1 + m2*m2 + m3*m3;
    float rg  = present ? __logf(fast_sqrt(msq) + 1.0f) : 0.0f;
    float l_reg = warpsum(rg) / fmaxf((float)num_instance, 1.0f) * REG_W;

    if (l == 0) {
        float loss = l_agg + l_dis + l_reg;
        out[b] = (num_instance <= 1) ? 0.0f : loss;
    }
}

extern "C" void kernel_launch(void* const* d_in, const int* in_sizes, int n_in,
                              void* d_out, int out_size) {
    const float* emb  = (const float*)d_in[0];
    const int*   inst = (const int*)d_in[1];
    const float* ker  = (const float*)d_in[2];
    const float* tmk  = (const float*)d_in[3];
    float* out = (float*)d_out;

    dim3 grid(GX, B);             // 736 blocks, all resident (5/SM cap, 48 regs)
    k_fused<<<grid, 256>>>(emb, inst, ker, tmk, out);
}